// round 17
// baseline (speedup 1.0000x reference)
#include <cuda_runtime.h>
#include <cuda_fp16.h>
#include <cstdint>

#define B_  8
#define N_  1024
#define C_  768
#define H_  12
#define HD_ 64
#define BH_ (B_*H_)          // 96
#define M_  (B_*N_)          // 8192
constexpr float SCALE = 0.125f;  // 64^-0.5

// ---- scratch (all fp16 operand chains) ----
__device__ __half g_qh[B_*H_*N_*HD_];   // [b][h][n][d]  fp16, pre-scaled
__device__ __half g_kh[B_*H_*N_*HD_];   // [b][h][n][d]  fp16
__device__ __half g_vh[B_*H_*HD_*N_];   // [b][h][d][n]  fp16, transposed
__device__ __half g_ctxh[B_*N_*C_];     // [b][n][c]     fp16
__device__ __half g_xh[M_*C_];          // x fp16
__device__ __half g_wqkvTh[3*C_*C_];    // w_qkv^T [n][k] fp16
__device__ __half g_woutTh[C_*C_];      // w_out^T [n][k] fp16

// ---- helpers ----
__device__ __forceinline__ uint32_t pack_f16x2(float a, float b) {
    uint32_t u; asm("cvt.rn.f16x2.f32 %0, %1, %2;" : "=r"(u) : "f"(b), "f"(a)); return u;
}
__device__ __forceinline__ void ldsm4(uint32_t& r0, uint32_t& r1, uint32_t& r2, uint32_t& r3,
                                      const uint32_t* p) {
    uint32_t a = (uint32_t)__cvta_generic_to_shared(p);
    asm volatile("ldmatrix.sync.aligned.m8n8.x4.shared.b16 {%0,%1,%2,%3}, [%4];"
                 : "=r"(r0), "=r"(r1), "=r"(r2), "=r"(r3) : "r"(a));
}
__device__ __forceinline__ void mma16(float* c, const uint32_t* a, const uint32_t* b) {
    asm volatile("mma.sync.aligned.m16n8k16.row.col.f32.f16.f16.f32 "
                 "{%0,%1,%2,%3},{%4,%5,%6,%7},{%8,%9},{%0,%1,%2,%3};"
                 : "+f"(c[0]), "+f"(c[1]), "+f"(c[2]), "+f"(c[3])
                 : "r"(a[0]), "r"(a[1]), "r"(a[2]), "r"(a[3]), "r"(b[0]), "r"(b[1]));
}
__device__ __forceinline__ void cpasync16(uint32_t* dst, const void* src) {
    uint32_t d = (uint32_t)__cvta_generic_to_shared(dst);
    asm volatile("cp.async.ca.shared.global [%0], [%1], 16;" :: "r"(d), "l"(src));
}
#define CP_COMMIT asm volatile("cp.async.commit_group;")
#define CP_WAIT0  asm volatile("cp.async.wait_group 0;")
#define CP_WAIT1  asm volatile("cp.async.wait_group 1;")

// half tiles: 64 halfs = 32 words per row; granule g 0..7 (8 halfs); word index
#define HG(r,g) ((r)*32 + ((((g) ^ ((r)&7)))<<2))

// ============================================================
// Prepass (verbatim round 16)
// ============================================================
__global__ __launch_bounds__(256) void cvt_x_h(const float* __restrict__ x) {
    const size_t i = ((size_t)blockIdx.x * 256 + threadIdx.x) * 8;
    float4 v0 = *(const float4*)(x + i);
    float4 v1 = *(const float4*)(x + i + 4);
    uint4 t = make_uint4(pack_f16x2(v0.x, v0.y), pack_f16x2(v0.z, v0.w),
                         pack_f16x2(v1.x, v1.y), pack_f16x2(v1.z, v1.w));
    *(uint4*)((uint32_t*)g_xh + i / 2) = t;
}

template <int COLS>
__global__ __launch_bounds__(256) void cvt_transpose_h(const float* __restrict__ src) {
    __half* dst = (COLS == 2304) ? g_wqkvTh : g_woutTh;
    __shared__ float tile[32][33];
    const int c0 = blockIdx.x * 32, r0 = blockIdx.y * 32;
    const int tx = threadIdx.x, ty = threadIdx.y;
#pragma unroll
    for (int u = 0; u < 4; u++)
        tile[ty + u * 8][tx] = src[(size_t)(r0 + ty + u * 8) * COLS + c0 + tx];
    __syncthreads();
#pragma unroll
    for (int u = 0; u < 4; u++) {
        const int c = c0 + ty + u * 8, r = r0 + tx;
        dst[(size_t)c * 768 + r] = __float2half_rn(tile[tx][ty + u * 8]);
    }
}

// ============================================================
// GEMM core fp16: 128x128x64 tiles, 3-STAGE cp.async ring.
// stage s: A at smem + s*8192, B at smem + s*8192 + 4096. 96KB total.
// ============================================================
__device__ __forceinline__ void gemm_fill_h(uint32_t* stage,
                                            const __half* A, const __half* BT,
                                            int by128, int bx128, int kt, int tid) {
#pragma unroll
    for (int u = 0; u < 4; u++) {
        const int g = tid + u * 256;
        const int row = g >> 3, kg = g & 7;
        cpasync16(&stage[HG(row, kg)],        A  + (size_t)(by128 + row) * 768 + kt + kg * 8);
        cpasync16(&stage[4096 + HG(row, kg)], BT + (size_t)(bx128 + row) * 768 + kt + kg * 8);
    }
}

__device__ __forceinline__ void gemm_core_h(const __half* A, const __half* BT,
                                            float acc[2][8][4]) {
    extern __shared__ uint32_t smem[];
    const int tid = threadIdx.x, lane = tid & 31, warp = tid >> 5;
    const int wm = warp >> 1, wn = warp & 1;
    const int by128 = blockIdx.y * 128, bx128 = blockIdx.x * 128;
    const int lrow = (lane & 7) + ((lane >> 3) & 1) * 8;
    const int lgr  = lane >> 4;

    gemm_fill_h(smem,        A, BT, by128, bx128, 0,  tid); CP_COMMIT;
    gemm_fill_h(smem + 8192, A, BT, by128, bx128, 64, tid); CP_COMMIT;

    for (int t = 0; t < 12; t++) {
        if (t < 10) { CP_WAIT1; } else { CP_WAIT0; }
        __syncthreads();
        if (t < 10) {
            gemm_fill_h(smem + ((t + 2) % 3) * 8192, A, BT, by128, bx128, (t + 2) * 64, tid);
            CP_COMMIT;
        }
        const uint32_t* Ab = smem + (t % 3) * 8192;
        const uint32_t* Bb = Ab + 4096;
#pragma unroll
        for (int kc = 0; kc < 4; kc++) {
            uint32_t a[2][4], b[8][2];
            const int gg = kc * 2 + lgr;
#pragma unroll
            for (int i = 0; i < 2; i++) {
                const int row = wm * 32 + i * 16 + lrow;
                ldsm4(a[i][0], a[i][1], a[i][2], a[i][3], &Ab[HG(row, gg)]);
            }
#pragma unroll
            for (int jp = 0; jp < 4; jp++) {
                const int row = wn * 64 + jp * 16 + lrow;
                ldsm4(b[2 * jp][0], b[2 * jp + 1][0], b[2 * jp][1], b[2 * jp + 1][1],
                      &Bb[HG(row, gg)]);
            }
#pragma unroll
            for (int i = 0; i < 2; i++)
#pragma unroll
                for (int j = 0; j < 8; j++) mma16(acc[i][j], a[i], b[j]);
        }
    }
}

// ============================================================
// Kernel 1: QKV GEMM (epilogue verbatim round 16)
// ============================================================
__global__ __launch_bounds__(256, 2) void qkv_gemm() {
    float acc[2][8][4];
#pragma unroll
    for (int i = 0; i < 2; i++)
#pragma unroll
        for (int j = 0; j < 8; j++)
#pragma unroll
            for (int r = 0; r < 4; r++) acc[i][j][r] = 0.f;

    gemm_core_h(g_xh, g_wqkvTh, acc);

    const int tid = threadIdx.x, lane = tid & 31, warp = tid >> 5;
    const int wm = warp >> 1, wn = warp & 1;
    const int n0 = blockIdx.x * 128 + wn * 64;
    const int sec = n0 / 768;
    const int h = (n0 - sec * 768) >> 6;
#pragma unroll
    for (int i = 0; i < 2; i++)
#pragma unroll
        for (int li = 0; li < 2; li++) {
            const int m = blockIdx.y * 128 + wm * 32 + i * 16 + li * 8 + (lane >> 2);
            const int b = m >> 10, tok = m & 1023;
            if (sec == 0) {
                uint32_t* base = (uint32_t*)g_qh +
                    ((size_t)(b * H_ + h) * 1024 + tok) * 32 + (lane & 3);
#pragma unroll
                for (int j = 0; j < 8; j++)
                    base[j * 4] = pack_f16x2(acc[i][j][li * 2] * SCALE,
                                             acc[i][j][li * 2 + 1] * SCALE);
            } else if (sec == 1) {
                uint32_t* base = (uint32_t*)g_kh +
                    ((size_t)(b * H_ + h) * 1024 + tok) * 32 + (lane & 3);
#pragma unroll
                for (int j = 0; j < 8; j++)
                    base[j * 4] = pack_f16x2(acc[i][j][li * 2], acc[i][j][li * 2 + 1]);
            } else {
                __half* base = g_vh + (size_t)(b * H_ + h) * 65536 + tok;
#pragma unroll
                for (int j = 0; j < 8; j++) {
                    const int d = j * 8 + 2 * (lane & 3);
                    base[(size_t)d * 1024]       = __float2half_rn(acc[i][j][li * 2]);
                    base[(size_t)(d + 1) * 1024] = __float2half_rn(acc[i][j][li * 2 + 1]);
                }
            }
        }
}

// ============================================================
// Kernel 2: flash attention fp16 — 3-STAGE K/V ring.
// smem: Q [0,4096) | stage s: K at 4096+s*4096, V at +2048 | P at 16384.
// Total 20480 words = 80KB -> 2 CTAs/SM.
// ============================================================
__device__ __forceinline__ void attn_loadKV(uint32_t* stage,
                                            const __half* kbase, const __half* vbase,
                                            int kt, int tid) {
#pragma unroll
    for (int u = 0; u < 2; u++) {
        const int g = tid + u * 256;
        const int row = g >> 3, kg = g & 7;
        cpasync16(&stage[HG(row, kg)],        kbase + (size_t)(kt + row) * 64 + kg * 8);
        cpasync16(&stage[2048 + HG(row, kg)], vbase + (size_t)row * 1024 + kt + kg * 8);
    }
}

__global__ __launch_bounds__(256, 2) void attn_kernel() {
    extern __shared__ uint32_t smem[];
    uint32_t* Qs = smem;             // 128*32
    uint32_t* Ps = smem + 16384;     // 128*32
    const int tid = threadIdx.x, lane = tid & 31, warp = tid >> 5;
    const int q0 = blockIdx.x * 128, bh = blockIdx.y;
    const __half* qbase = g_qh + (size_t)bh * 65536 + (size_t)q0 * 64;
    const __half* kbase = g_kh + (size_t)bh * 65536;
    const __half* vbase = g_vh + (size_t)bh * 65536;

    // group 0: Q + K/V stage 0 ; group 1: K/V stage 1
#pragma unroll
    for (int u = 0; u < 4; u++) {
        const int g = tid + u * 256;
        const int row = g >> 3, kg = g & 7;
        cpasync16(&Qs[HG(row, kg)], qbase + (size_t)row * 64 + kg * 8);
    }
    attn_loadKV(smem + 4096, kbase, vbase, 0, tid); CP_COMMIT;
    attn_loadKV(smem + 8192, kbase, vbase, 64, tid); CP_COMMIT;

    float o[8][4];
#pragma unroll
    for (int j = 0; j < 8; j++)
#pragma unroll
        for (int r = 0; r < 4; r++) o[j][r] = 0.f;
    float mA = -1e30f, mB = -1e30f, lA = 0.f, lB = 0.f;

    const int lrow = (lane & 7) + ((lane >> 3) & 1) * 8;
    const int lgr  = lane >> 4;

    for (int t = 0; t < 16; t++) {
        if (t < 14) { CP_WAIT1; } else { CP_WAIT0; }
        __syncthreads();
        if (t < 14) {
            attn_loadKV(smem + 4096 + ((t + 2) % 3) * 4096, kbase, vbase, (t + 2) * 64, tid);
            CP_COMMIT;
        }
        const uint32_t* Kb = smem + 4096 + (t % 3) * 4096;
        const uint32_t* Vb = Kb + 2048;

        // S = Q K^T
        float s[8][4];
#pragma unroll
        for (int j = 0; j < 8; j++)
#pragma unroll
            for (int r = 0; r < 4; r++) s[j][r] = 0.f;
#pragma unroll
        for (int kc = 0; kc < 4; kc++) {
            uint32_t a[4], b[8][2];
            const int g = kc * 2 + lgr;
            {
                const int row = warp * 16 + lrow;
                ldsm4(a[0], a[1], a[2], a[3], &Qs[HG(row, g)]);
            }
#pragma unroll
            for (int jp = 0; jp < 4; jp++) {
                const int row = jp * 16 + lrow;
                ldsm4(b[2 * jp][0], b[2 * jp + 1][0], b[2 * jp][1], b[2 * jp + 1][1],
                      &Kb[HG(row, g)]);
            }
#pragma unroll
            for (int j = 0; j < 8; j++) mma16(s[j], a, b[j]);
        }

        // online softmax
        float mxa = -1e30f, mxb = -1e30f;
#pragma unroll
        for (int j = 0; j < 8; j++) {
            mxa = fmaxf(mxa, fmaxf(s[j][0], s[j][1]));
            mxb = fmaxf(mxb, fmaxf(s[j][2], s[j][3]));
        }
#pragma unroll
        for (int off = 1; off <= 2; off <<= 1) {
            mxa = fmaxf(mxa, __shfl_xor_sync(0xffffffffu, mxa, off));
            mxb = fmaxf(mxb, __shfl_xor_sync(0xffffffffu, mxb, off));
        }
        const float mnA = fmaxf(mA, mxa), mnB = fmaxf(mB, mxb);
        const float facA = __expf(mA - mnA), facB = __expf(mB - mnB);
        mA = mnA; mB = mnB;
        float sa = 0.f, sb = 0.f;
#pragma unroll
        for (int j = 0; j < 8; j++) {
            s[j][0] = __expf(s[j][0] - mA); s[j][1] = __expf(s[j][1] - mA);
            s[j][2] = __expf(s[j][2] - mB); s[j][3] = __expf(s[j][3] - mB);
            sa += s[j][0] + s[j][1]; sb += s[j][2] + s[j][3];
        }
#pragma unroll
        for (int off = 1; off <= 2; off <<= 1) {
            sa += __shfl_xor_sync(0xffffffffu, sa, off);
            sb += __shfl_xor_sync(0xffffffffu, sb, off);
        }
        lA = lA * facA + sa; lB = lB * facB + sb;
#pragma unroll
        for (int j = 0; j < 8; j++) {
            o[j][0] *= facA; o[j][1] *= facA; o[j][2] *= facB; o[j][3] *= facB;
        }

        // store P (fp16) into warp-private rows of Ps
        {
            const int ra = warp * 16 + (lane >> 2), rb = ra + 8;
#pragma unroll
            for (int j = 0; j < 8; j++) {
                Ps[HG(ra, j) + (lane & 3)] = pack_f16x2(s[j][0], s[j][1]);
                Ps[HG(rb, j) + (lane & 3)] = pack_f16x2(s[j][2], s[j][3]);
            }
        }
        __syncwarp();

        // O += P V
#pragma unroll
        for (int kc = 0; kc < 4; kc++) {
            uint32_t a[4], b[8][2];
            const int g = kc * 2 + lgr;
            {
                const int row = warp * 16 + lrow;
                ldsm4(a[0], a[1], a[2], a[3], &Ps[HG(row, g)]);
            }
#pragma unroll
            for (int jp = 0; jp < 4; jp++) {
                const int row = jp * 16 + lrow;
                ldsm4(b[2 * jp][0], b[2 * jp + 1][0], b[2 * jp][1], b[2 * jp + 1][1],
                      &Vb[HG(row, g)]);
            }
#pragma unroll
            for (int j = 0; j < 8; j++) mma16(o[j], a, b[j]);
        }
    }

    // normalize + write ctx as fp16
    const int b = bh / H_, h = bh - b * H_;
    const int ra = warp * 16 + (lane >> 2);
    const float invA = 1.f / lA, invB = 1.f / lB;
    uint32_t* pa = (uint32_t*)g_ctxh + ((size_t)(b * 1024) + q0 + ra) * 384 + h * 32 + (lane & 3);
    uint32_t* pb = (uint32_t*)g_ctxh + ((size_t)(b * 1024) + q0 + ra + 8) * 384 + h * 32 + (lane & 3);
#pragma unroll
    for (int j = 0; j < 8; j++) {
        pa[j * 4] = pack_f16x2(o[j][0] * invA, o[j][1] * invA);
        pb[j * 4] = pack_f16x2(o[j][2] * invB, o[j][3] * invB);
    }
}

// ============================================================
// Kernel 3: out projection (epilogue verbatim round 16)
// ============================================================
__global__ __launch_bounds__(256, 2) void out_gemm(const float* __restrict__ bias,
                                                   float* __restrict__ out) {
    float acc[2][8][4];
#pragma unroll
    for (int i = 0; i < 2; i++)
#pragma unroll
        for (int j = 0; j < 8; j++)
#pragma unroll
            for (int r = 0; r < 4; r++) acc[i][j][r] = 0.f;

    gemm_core_h(g_ctxh, g_woutTh, acc);

    const int tid = threadIdx.x, lane = tid & 31, warp = tid >> 5;
    const int wm = warp >> 1, wn = warp & 1;
    const int n0 = blockIdx.x * 128 + wn * 64 + 2 * (lane & 3);
#pragma unroll
    for (int i = 0; i < 2; i++)
#pragma unroll
        for (int li = 0; li < 2; li++) {
            const int m = blockIdx.y * 128 + wm * 32 + i * 16 + li * 8 + (lane >> 2);
            float* op = out + (size_t)m * 768 + n0;
#pragma unroll
            for (int j = 0; j < 8; j++) {
                float2 bb = *(const float2*)(bias + n0 + j * 8);
                *(float2*)(op + j * 8) =
                    make_float2(acc[i][j][li * 2] + bb.x, acc[i][j][li * 2 + 1] + bb.y);
            }
        }
}

// ============================================================
extern "C" void kernel_launch(void* const* d_in, const int* in_sizes, int n_in,
                              void* d_out, int out_size) {
    const float* x     = (const float*)d_in[0];
    const float* w_qkv = (const float*)d_in[1];
    const float* w_out = (const float*)d_in[2];
    const float* b_out = (const float*)d_in[3];
    float* out = (float*)d_out;

    cudaFuncSetAttribute(qkv_gemm, cudaFuncAttributeMaxDynamicSharedMemorySize, 98304);
    cudaFuncSetAttribute(out_gemm, cudaFuncAttributeMaxDynamicSharedMemorySize, 98304);
    cudaFuncSetAttribute(attn_kernel, cudaFuncAttributeMaxDynamicSharedMemorySize, 81920);

    cvt_x_h<<<M_ * C_ / 2048, 256>>>(x);
    cvt_transpose_h<2304><<<dim3(2304 / 32, 768 / 32), dim3(32, 8)>>>(w_qkv);
    cvt_transpose_h<768><<<dim3(768 / 32, 768 / 32), dim3(32, 8)>>>(w_out);
    qkv_gemm<<<dim3(2304 / 128, M_ / 128), 256, 98304>>>();
    attn_kernel<<<dim3(N_ / 128, BH_), 256, 81920>>>();
    out_gemm<<<dim3(768 / 128, M_ / 128), 256, 98304>>>(b_out, out);
}